// round 5
// baseline (speedup 1.0000x reference)
#include <cuda_runtime.h>
#include <cuda_fp16.h>

#define SMEM_BYTES 209408

namespace {

constexpr int THsz = 1536;

// ---------- device scratch ----------
__device__ __half   g_wpack[3][786432];   // packed B-frags per gemm
__device__ float    g_yctr[512 * THsz];   // y@w_ih1[:,1:]^T + b_ih1
__device__ __half   g_s0h[2][512 * 512];
__device__ __half   g_s1h[2][512 * 512];
__device__ float    g_fcpart[512 * 32];
__device__ unsigned g_bar[4096];          // 4 groups x 1024 slots

// ---------- helpers ----------
__device__ __forceinline__ unsigned su32(const void* p) {
  return (unsigned)__cvta_generic_to_shared(p);
}
__device__ __forceinline__ void cp16(unsigned d, const void* s) {
  asm volatile("cp.async.cg.shared.global [%0], [%1], 16;\n" :: "r"(d), "l"(s));
}
__device__ __forceinline__ void cpcommit() { asm volatile("cp.async.commit_group;\n"); }
template <int N> __device__ __forceinline__ void cpwait() {
  asm volatile("cp.async.wait_group %0;\n" :: "n"(N));
}
__device__ __forceinline__ void ldsm4(unsigned& r0, unsigned& r1, unsigned& r2,
                                      unsigned& r3, unsigned a) {
  asm volatile("ldmatrix.sync.aligned.m8n8.x4.shared.b16 {%0,%1,%2,%3}, [%4];\n"
               : "=r"(r0), "=r"(r1), "=r"(r2), "=r"(r3) : "r"(a));
}
__device__ __forceinline__ void mma16816(float* c, unsigned a0, unsigned a1,
                                         unsigned a2, unsigned a3,
                                         unsigned b0, unsigned b1) {
  asm volatile(
      "mma.sync.aligned.m16n8k16.row.col.f32.f16.f16.f32 "
      "{%0,%1,%2,%3},{%4,%5,%6,%7},{%8,%9},{%0,%1,%2,%3};\n"
      : "+f"(c[0]), "+f"(c[1]), "+f"(c[2]), "+f"(c[3])
      : "r"(a0), "r"(a1), "r"(a2), "r"(a3), "r"(b0), "r"(b1));
}
__device__ __forceinline__ float sigm(float x) {
  float t, r;
  asm("ex2.approx.f32 %0, %1;" : "=f"(t) : "f"(-1.4426950408889634f * x));
  asm("rcp.approx.f32 %0, %1;" : "=f"(r) : "f"(1.0f + t));
  return r;
}
__device__ __forceinline__ float tanh_(float x) {
  x = fminf(fmaxf(x, -15.f), 15.f);
  float t, r;
  asm("ex2.approx.f32 %0, %1;" : "=f"(t) : "f"(-2.8853900817779268f * x));
  asm("rcp.approx.f32 %0, %1;" : "=f"(r) : "f"(1.0f + t));
  return (1.0f - t) * r;
}
__device__ __forceinline__ void groupbar(unsigned* ctr) {
  __syncthreads();
  if (threadIdx.x == 0) {
    asm volatile("red.release.gpu.global.add.u32 [%0], 1;" :: "l"(ctr) : "memory");
    unsigned v;
    do {
      asm volatile("ld.acquire.gpu.global.u32 %0, [%1];" : "=r"(v) : "l"(ctr) : "memory");
    } while (v < 32u);
  }
  __syncthreads();
}

// ---------- prep kernels ----------
__global__ void prep_zero() {
  unsigned i = blockIdx.x * 256u + threadIdx.x;
  if (i < 4096u) g_bar[i] = 0u;
}

__global__ void prep_pack(const float* __restrict__ whh1,
                          const float* __restrict__ wih2,
                          const float* __restrict__ whh2) {
  unsigned t = blockIdx.x * 256u + threadIdx.x;
  if (t >= 589824u) return;
  unsigned lane = t & 31u, kt = (t >> 5) & 31u, nt = (t >> 10) & 1u;
  unsigned g = (t >> 11) % 3u, hs = (t / 6144u) & 31u, gm = t / 196608u;
  const float* W = (gm == 0) ? whh1 : (gm == 1 ? wih2 : whh2);
  int j = (int)(g * 512u + hs * 16u + nt * 8u + (lane >> 2));
  int k = (int)(kt * 16u + (lane & 3u) * 2u);
  const float* wr = W + (size_t)j * 512;
  __half* dst = g_wpack[gm] + (size_t)hs * 24576u +
                ((((g * 2u + nt) * 32u + kt) * 32u + lane) << 2);
  *(__half2*)(dst)     = __floats2half2_rn(wr[k], wr[k + 1]);
  *(__half2*)(dst + 2) = __floats2half2_rn(wr[k + 8], wr[k + 9]);
}

__global__ void prep_yctr(const float* __restrict__ y,
                          const float* __restrict__ wih1,
                          const float* __restrict__ bih1) {
  __shared__ float ys[127];
  int b = blockIdx.x;
  for (int c = threadIdx.x; c < 127; c += blockDim.x) ys[c] = y[b * 127 + c];
  __syncthreads();
  for (int j = threadIdx.x; j < THsz; j += blockDim.x) {
    const float* wr = wih1 + (size_t)j * 128 + 1;
    float s = bih1[j];
#pragma unroll 4
    for (int c = 0; c < 127; c++) s += ys[c] * wr[c];
    g_yctr[(size_t)b * THsz + j] = s;
  }
}

// ---------- GEMM slice: C[3][2][4] = A(128x512) @ Wslice(48x512)^T ----------
__device__ __forceinline__ void gemm_slice(const __half* __restrict__ Ag,
                                           const unsigned* __restrict__ wsmu,
                                           unsigned stage_u32, int tid, int w,
                                           int lane, float (&C)[3][2][4]) {
#pragma unroll
  for (int g = 0; g < 3; g++)
#pragma unroll
    for (int nt = 0; nt < 2; nt++)
#pragma unroll
      for (int e = 0; e < 4; e++) C[g][nt][e] = 0.f;

  const int crow = tid >> 3;
  const int ccol = (tid & 7) << 3;
  const unsigned dof = (unsigned)((crow * 72 + ccol) * 2);
  const __half* srow = Ag + crow * 512 + ccol;
#pragma unroll
  for (int i = 0; i < 4; i++)
    cp16(stage_u32 + dof + i * (32 * 72 * 2), srow + i * (32 * 512));
  cpcommit();

  const unsigned arow =
      stage_u32 + (unsigned)(((w * 16 + (lane & 15)) * 72 + ((lane >> 4) << 3)) * 2);

  for (int ch = 0; ch < 8; ch++) {
    if (ch < 7) {
      unsigned sb = stage_u32 + (unsigned)(((ch + 1) & 1) * (128 * 72 * 2));
      const __half* s = srow + (ch + 1) * 64;
#pragma unroll
      for (int i = 0; i < 4; i++)
        cp16(sb + dof + i * (32 * 72 * 2), s + i * (32 * 512));
      cpcommit();
      cpwait<1>();
    } else {
      cpwait<0>();
    }
    __syncthreads();
    unsigned ab = arow + (unsigned)((ch & 1) * (128 * 72 * 2));
#pragma unroll
    for (int k4 = 0; k4 < 4; k4++) {
      unsigned a0, a1, a2, a3;
      ldsm4(a0, a1, a2, a3, ab + k4 * 32);
      const int ktg = ch * 4 + k4;
#pragma unroll
      for (int g = 0; g < 3; g++)
#pragma unroll
        for (int nt = 0; nt < 2; nt++) {
          const uint2 bv = *reinterpret_cast<const uint2*>(
              wsmu + ((((g * 2 + nt) * 32 + ktg) * 32 + lane) << 1));
          mma16816(C[g][nt], a0, a1, a2, a3, bv.x, bv.y);
        }
    }
    __syncthreads();
  }
}

// ---------- main persistent kernel ----------
__global__ void __launch_bounds__(256, 1)
gen_main(const float* __restrict__ z1, const float* __restrict__ y,
         const float* __restrict__ x, const float* __restrict__ hid1,
         const float* __restrict__ wih1, const float* __restrict__ bhh1g,
         const float* __restrict__ bih2g, const float* __restrict__ bhh2g,
         const float* __restrict__ wfc, const float* __restrict__ bfcp,
         float* __restrict__ dout) {
  extern __shared__ unsigned char smem[];
  __half* wsm = (__half*)smem;                            // 147456 B
  const unsigned stage_u32 = su32(smem + 147456);         // 36864 B
  float* yctr = (float*)(smem + 184320);                  // 24576 B
  float* osm  = (float*)(smem + 208896);                  // 512 B
  const unsigned* wsmu = (const unsigned*)wsm;

  const int cta = blockIdx.x;
  const int bt = cta >> 5, hs = cta & 31;
  const int tid = threadIdx.x;
  const int w = tid >> 5, lane = tid & 31;

  // weight slices -> SMEM (L2 path)
  {
    unsigned dbase = su32(wsm);
    for (int i = tid; i < 9216; i += 256) {
      int gm = i / 3072, q = i - gm * 3072;
      cp16(dbase + (unsigned)((gm * 24576 + q * 8) * 2),
           g_wpack[gm] + (size_t)hs * 24576 + q * 8);
    }
    cpcommit();
  }
  // ycontrib slice -> SMEM: [g][brow 0..127][hcol 0..15]
  for (int m = tid; m < 3 * 128 * 16; m += 256) {
    int g = m >> 11, rr = m & 2047, b = rr >> 4, hh = rr & 15;
    yctr[m] = g_yctr[(size_t)(bt * 128 + b) * THsz + g * 512 + hs * 16 + hh];
  }

  const int blo = w * 16 + (lane >> 2);
  const int h0 = (lane & 3) * 2;
  float bhh1[3][4], wc0[3][4], brz2[2][4], bin2[4], bhn2[4], wfcv[4];
#pragma unroll
  for (int g = 0; g < 3; g++)
#pragma unroll
    for (int i = 0; i < 4; i++) {
      int hl = (i >> 1) * 8 + h0 + (i & 1);
      int j = g * 512 + hs * 16 + hl;
      bhh1[g][i] = bhh1g[j];
      wc0[g][i] = wih1[(size_t)j * 128];
      if (g < 2) brz2[g][i] = bih2g[j] + bhh2g[j];
      else { bin2[i] = bih2g[j]; bhn2[i] = bhh2g[j]; }
    }
#pragma unroll
  for (int i = 0; i < 4; i++)
    wfcv[i] = wfc[hs * 16 + (i >> 1) * 8 + h0 + (i & 1)];
  const float bfc = bfcp[0];

  // init fp32 states + fp16 copies into buffer 0
  float s0f[2][4], s1f[2][4];
#pragma unroll
  for (int bh = 0; bh < 2; bh++) {
    int gb = bt * 128 + blo + bh * 8;
#pragma unroll
    for (int i = 0; i < 4; i++) {
      int gh = hs * 16 + (i >> 1) * 8 + h0 + (i & 1);
      s0f[bh][i] = (gh < 385) ? z1[(size_t)gb * 385 + gh]
                              : y[(size_t)gb * 127 + (gh - 385)];
      s1f[bh][i] = hid1[(size_t)gb * 512 + gh];
    }
#pragma unroll
    for (int nt = 0; nt < 2; nt++) {
      int gh = hs * 16 + nt * 8 + h0;
      *(__half2*)&g_s0h[0][(size_t)gb * 512 + gh] =
          __floats2half2_rn(s0f[bh][nt * 2], s0f[bh][nt * 2 + 1]);
      *(__half2*)&g_s1h[0][(size_t)gb * 512 + gh] =
          __floats2half2_rn(s1f[bh][nt * 2], s1f[bh][nt * 2 + 1]);
    }
  }
  if (tid < 128) osm[tid] = x[bt * 128 + tid];
  cpwait<0>();
  __syncthreads();

  unsigned* barp = &g_bar[bt * 1024];
  groupbar(barp + 512);  // init states visible group-wide

  float Cg1[3][2][4], Cg2[3][2][4];

  for (int t = 0; t < 256; t++) {
    const int pb = t & 1, nb = pb ^ 1;
    const __half* s0p = g_s0h[pb] + (size_t)bt * 128 * 512;
    const __half* s1p = g_s1h[pb] + (size_t)bt * 128 * 512;

    // phase 1: gh1 = s0 @ whh1^T (slice 0), gh2 = s1 @ whh2^T (slice 2)
    gemm_slice(s0p, wsmu, stage_u32, tid, w, lane, Cg1);
    gemm_slice(s1p, wsmu + 24576, stage_u32, tid, w, lane, Cg2);

    // phase 2: cell-1 elementwise -> s0', write fp16 buf nb
    {
      float ob[2] = {osm[blo], osm[blo + 8]};
#pragma unroll
      for (int bh = 0; bh < 2; bh++) {
        int brow = blo + bh * 8;
#pragma unroll
        for (int i = 0; i < 4; i++) {
          int nt = i >> 1, e = bh * 2 + (i & 1);
          int yi = brow * 16 + nt * 8 + h0 + (i & 1);
          float gr = yctr[yi]        + ob[bh] * wc0[0][i] + Cg1[0][nt][e] + bhh1[0][i];
          float gz = yctr[2048 + yi] + ob[bh] * wc0[1][i] + Cg1[1][nt][e] + bhh1[1][i];
          float gn = yctr[4096 + yi] + ob[bh] * wc0[2][i];
          float r = sigm(gr), z = sigm(gz);
          float n = tanh_(gn + r * (Cg1[2][nt][e] + bhh1[2][i]));
          s0f[bh][i] = (1.f - z) * n + z * s0f[bh][i];
        }
        int gb = bt * 128 + brow;
#pragma unroll
        for (int nt = 0; nt < 2; nt++)
          *(__half2*)&g_s0h[nb][(size_t)gb * 512 + hs * 16 + nt * 8 + h0] =
              __floats2half2_rn(s0f[bh][nt * 2], s0f[bh][nt * 2 + 1]);
      }
    }
    groupbar(barp + t * 2);

    // phase 4: gi2 = s0' @ wih2^T (slice 1)  (reuse Cg1)
    gemm_slice(g_s0h[nb] + (size_t)bt * 128 * 512, wsmu + 12288, stage_u32,
               tid, w, lane, Cg1);

    // phase 5: cell-2 elementwise -> s1', fc partials
    {
#pragma unroll
      for (int bh = 0; bh < 2; bh++) {
        float p = 0.f;
#pragma unroll
        for (int i = 0; i < 4; i++) {
          int nt = i >> 1, e = bh * 2 + (i & 1);
          float r = sigm(Cg1[0][nt][e] + Cg2[0][nt][e] + brz2[0][i]);
          float z = sigm(Cg1[1][nt][e] + Cg2[1][nt][e] + brz2[1][i]);
          float n = tanh_(Cg1[2][nt][e] + bin2[i] + r * (Cg2[2][nt][e] + bhn2[i]));
          s1f[bh][i] = (1.f - z) * n + z * s1f[bh][i];
          p += s1f[bh][i] * wfcv[i];
        }
        int gb = bt * 128 + blo + bh * 8;
#pragma unroll
        for (int nt = 0; nt < 2; nt++)
          *(__half2*)&g_s1h[nb][(size_t)gb * 512 + hs * 16 + nt * 8 + h0] =
              __floats2half2_rn(s1f[bh][nt * 2], s1f[bh][nt * 2 + 1]);
        p += __shfl_xor_sync(0xffffffffu, p, 1);
        p += __shfl_xor_sync(0xffffffffu, p, 2);
        if ((lane & 3) == 0) __stcg(&g_fcpart[(size_t)gb * 32 + hs], p);
      }
    }
    groupbar(barp + t * 2 + 1);

    // phase 7: o = relu(bfc + sum partials)
    if (tid < 128) {
      const float* fp = &g_fcpart[(size_t)(bt * 128 + tid) * 32];
      float s = bfc;
#pragma unroll 8
      for (int k = 0; k < 32; k++) s += __ldcg(fp + k);
      float o = fmaxf(s, 0.f);
      osm[tid] = o;
      if (hs == 0) dout[(size_t)(bt * 128 + tid) * 256 + t] = o;
    }
  }
}

}  // namespace

extern "C" void kernel_launch(void* const* d_in, const int* in_sizes, int n_in,
                              void* d_out, int out_size) {
  const float* z1   = (const float*)d_in[0];
  const float* y    = (const float*)d_in[1];
  const float* x    = (const float*)d_in[2];
  const float* h1   = (const float*)d_in[3];
  const float* wih1 = (const float*)d_in[4];
  const float* whh1 = (const float*)d_in[5];
  const float* bih1 = (const float*)d_in[6];
  const float* bhh1 = (const float*)d_in[7];
  const float* wih2 = (const float*)d_in[8];
  const float* whh2 = (const float*)d_in[9];
  const float* bih2 = (const float*)d_in[10];
  const float* bhh2 = (const float*)d_in[11];
  const float* wfc  = (const float*)d_in[12];
  const float* bfc  = (const float*)d_in[13];

  cudaFuncSetAttribute(gen_main, cudaFuncAttributeMaxDynamicSharedMemorySize,
                       SMEM_BYTES);

  prep_zero<<<16, 256>>>();
  prep_pack<<<2304, 256>>>(whh1, wih2, whh2);
  prep_yctr<<<512, 256>>>(y, wih1, bih1);
  gen_main<<<128, 256, SMEM_BYTES>>>(z1, y, x, h1, wih1, bhh1, bih2, bhh2,
                                     wfc, bfc, (float*)d_out);
}

// round 6
// speedup vs baseline: 1.0042x; 1.0042x over previous
#include <cuda_runtime.h>
#include <cuda_fp16.h>

#define SMEM_BYTES 209408

namespace {

constexpr int THsz = 1536;

// ---------- device scratch ----------
__device__ __half   g_wpack[3][786432];   // packed B-frags per gemm
__device__ float    g_yctr[512 * THsz];   // y@w_ih1[:,1:]^T + b_ih1
__device__ __half   g_s0h[2][512 * 512];
__device__ __half   g_s1h[2][512 * 512];
__device__ float    g_fcpart[512 * 32];
__device__ unsigned g_bar[4096];          // 4 groups x 1024 slots

// ---------- helpers ----------
__device__ __forceinline__ unsigned su32(const void* p) {
  return (unsigned)__cvta_generic_to_shared(p);
}
__device__ __forceinline__ void cp16(unsigned d, const void* s) {
  asm volatile("cp.async.cg.shared.global [%0], [%1], 16;\n" :: "r"(d), "l"(s));
}
__device__ __forceinline__ void cpcommit() { asm volatile("cp.async.commit_group;\n"); }
template <int N> __device__ __forceinline__ void cpwait() {
  asm volatile("cp.async.wait_group %0;\n" :: "n"(N));
}
__device__ __forceinline__ void ldsm4(unsigned& r0, unsigned& r1, unsigned& r2,
                                      unsigned& r3, unsigned a) {
  asm volatile("ldmatrix.sync.aligned.m8n8.x4.shared.b16 {%0,%1,%2,%3}, [%4];\n"
               : "=r"(r0), "=r"(r1), "=r"(r2), "=r"(r3) : "r"(a));
}
__device__ __forceinline__ void mma16816(float* c, unsigned a0, unsigned a1,
                                         unsigned a2, unsigned a3,
                                         unsigned b0, unsigned b1) {
  asm volatile(
      "mma.sync.aligned.m16n8k16.row.col.f32.f16.f16.f32 "
      "{%0,%1,%2,%3},{%4,%5,%6,%7},{%8,%9},{%0,%1,%2,%3};\n"
      : "+f"(c[0]), "+f"(c[1]), "+f"(c[2]), "+f"(c[3])
      : "r"(a0), "r"(a1), "r"(a2), "r"(a3), "r"(b0), "r"(b1));
}
__device__ __forceinline__ float sigm(float x) {
  float t, r;
  asm("ex2.approx.f32 %0, %1;" : "=f"(t) : "f"(-1.4426950408889634f * x));
  asm("rcp.approx.f32 %0, %1;" : "=f"(r) : "f"(1.0f + t));
  return r;
}
__device__ __forceinline__ float tanh_(float x) {
  x = fminf(fmaxf(x, -15.f), 15.f);
  float t, r;
  asm("ex2.approx.f32 %0, %1;" : "=f"(t) : "f"(-2.8853900817779268f * x));
  asm("rcp.approx.f32 %0, %1;" : "=f"(r) : "f"(1.0f + t));
  return (1.0f - t) * r;
}
__device__ __forceinline__ void groupbar(unsigned* ctr) {
  __syncthreads();
  if (threadIdx.x == 0) {
    asm volatile("red.release.gpu.global.add.u32 [%0], 1;" :: "l"(ctr) : "memory");
    unsigned v;
    do {
      asm volatile("ld.acquire.gpu.global.u32 %0, [%1];" : "=r"(v) : "l"(ctr) : "memory");
    } while (v < 32u);
  }
  __syncthreads();
}

// ---------- prep kernels ----------
__global__ void prep_zero() {
  unsigned i = blockIdx.x * 256u + threadIdx.x;
  if (i < 4096u) g_bar[i] = 0u;
}

__global__ void prep_pack(const float* __restrict__ whh1,
                          const float* __restrict__ wih2,
                          const float* __restrict__ whh2) {
  unsigned t = blockIdx.x * 256u + threadIdx.x;
  if (t >= 589824u) return;
  unsigned lane = t & 31u, kt = (t >> 5) & 31u, nt = (t >> 10) & 1u;
  unsigned g = (t >> 11) % 3u, hs = (t / 6144u) & 31u, gm = t / 196608u;
  const float* W = (gm == 0) ? whh1 : (gm == 1 ? wih2 : whh2);
  int j = (int)(g * 512u + hs * 16u + nt * 8u + (lane >> 2));
  int k = (int)(kt * 16u + (lane & 3u) * 2u);
  const float* wr = W + (size_t)j * 512;
  __half* dst = g_wpack[gm] + (size_t)hs * 24576u +
                ((((g * 2u + nt) * 32u + kt) * 32u + lane) << 2);
  *(__half2*)(dst)     = __floats2half2_rn(wr[k], wr[k + 1]);
  *(__half2*)(dst + 2) = __floats2half2_rn(wr[k + 8], wr[k + 9]);
}

__global__ void prep_yctr(const float* __restrict__ y,
                          const float* __restrict__ wih1,
                          const float* __restrict__ bih1) {
  __shared__ float ys[127];
  int b = blockIdx.x;
  for (int c = threadIdx.x; c < 127; c += blockDim.x) ys[c] = y[b * 127 + c];
  __syncthreads();
  for (int j = threadIdx.x; j < THsz; j += blockDim.x) {
    const float* wr = wih1 + (size_t)j * 128 + 1;
    float s = bih1[j];
#pragma unroll 4
    for (int c = 0; c < 127; c++) s += ys[c] * wr[c];
    g_yctr[(size_t)b * THsz + j] = s;
  }
}

// ---------- GEMM slice: C[3][2][4] = A(128x512) @ Wslice(48x512)^T ----------
__device__ __forceinline__ void gemm_slice(const __half* __restrict__ Ag,
                                           const unsigned* __restrict__ wsmu,
                                           unsigned stage_u32, int tid, int w,
                                           int lane, float (&C)[3][2][4]) {
#pragma unroll
  for (int g = 0; g < 3; g++)
#pragma unroll
    for (int nt = 0; nt < 2; nt++)
#pragma unroll
      for (int e = 0; e < 4; e++) C[g][nt][e] = 0.f;

  const int crow = tid >> 3;
  const int ccol = (tid & 7) << 3;
  const unsigned dof = (unsigned)((crow * 72 + ccol) * 2);
  const __half* srow = Ag + crow * 512 + ccol;
#pragma unroll
  for (int i = 0; i < 4; i++)
    cp16(stage_u32 + dof + i * (32 * 72 * 2), srow + i * (32 * 512));
  cpcommit();

  const unsigned arow =
      stage_u32 + (unsigned)(((w * 16 + (lane & 15)) * 72 + ((lane >> 4) << 3)) * 2);

  for (int ch = 0; ch < 8; ch++) {
    if (ch < 7) {
      unsigned sb = stage_u32 + (unsigned)(((ch + 1) & 1) * (128 * 72 * 2));
      const __half* s = srow + (ch + 1) * 64;
#pragma unroll
      for (int i = 0; i < 4; i++)
        cp16(sb + dof + i * (32 * 72 * 2), s + i * (32 * 512));
      cpcommit();
      cpwait<1>();
    } else {
      cpwait<0>();
    }
    __syncthreads();
    unsigned ab = arow + (unsigned)((ch & 1) * (128 * 72 * 2));
#pragma unroll
    for (int k4 = 0; k4 < 4; k4++) {
      unsigned a0, a1, a2, a3;
      ldsm4(a0, a1, a2, a3, ab + k4 * 32);
      const int ktg = ch * 4 + k4;
#pragma unroll
      for (int g = 0; g < 3; g++)
#pragma unroll
        for (int nt = 0; nt < 2; nt++) {
          const uint2 bv = *reinterpret_cast<const uint2*>(
              wsmu + ((((g * 2 + nt) * 32 + ktg) * 32 + lane) << 1));
          mma16816(C[g][nt], a0, a1, a2, a3, bv.x, bv.y);
        }
    }
    __syncthreads();
  }
}

// ---------- main persistent kernel ----------
__global__ void __launch_bounds__(256, 1)
gen_main(const float* __restrict__ z1, const float* __restrict__ y,
         const float* __restrict__ x, const float* __restrict__ hid1,
         const float* __restrict__ wih1, const float* __restrict__ bhh1g,
         const float* __restrict__ bih2g, const float* __restrict__ bhh2g,
         const float* __restrict__ wfc, const float* __restrict__ bfcp,
         float* __restrict__ dout) {
  extern __shared__ unsigned char smem[];
  __half* wsm = (__half*)smem;                            // 147456 B
  const unsigned stage_u32 = su32(smem + 147456);         // 36864 B
  float* yctr = (float*)(smem + 184320);                  // 24576 B
  float* osm  = (float*)(smem + 208896);                  // 512 B
  const unsigned* wsmu = (const unsigned*)wsm;

  const int cta = blockIdx.x;
  const int bt = cta >> 5, hs = cta & 31;
  const int tid = threadIdx.x;
  const int w = tid >> 5, lane = tid & 31;

  // weight slices -> SMEM (L2 path)
  {
    unsigned dbase = su32(wsm);
    for (int i = tid; i < 9216; i += 256) {
      int gm = i / 3072, q = i - gm * 3072;
      cp16(dbase + (unsigned)((gm * 24576 + q * 8) * 2),
           g_wpack[gm] + (size_t)hs * 24576 + q * 8);
    }
    cpcommit();
  }
  // ycontrib slice -> SMEM: [g][brow 0..127][hcol 0..15]
  for (int m = tid; m < 3 * 128 * 16; m += 256) {
    int g = m >> 11, rr = m & 2047, b = rr >> 4, hh = rr & 15;
    yctr[m] = g_yctr[(size_t)(bt * 128 + b) * THsz + g * 512 + hs * 16 + hh];
  }

  const int blo = w * 16 + (lane >> 2);
  const int h0 = (lane & 3) * 2;
  float bhh1[3][4], wc0[3][4], brz2[2][4], bin2[4], bhn2[4], wfcv[4];
#pragma unroll
  for (int g = 0; g < 3; g++)
#pragma unroll
    for (int i = 0; i < 4; i++) {
      int hl = (i >> 1) * 8 + h0 + (i & 1);
      int j = g * 512 + hs * 16 + hl;
      bhh1[g][i] = bhh1g[j];
      wc0[g][i] = wih1[(size_t)j * 128];
      if (g < 2) brz2[g][i] = bih2g[j] + bhh2g[j];
      else { bin2[i] = bih2g[j]; bhn2[i] = bhh2g[j]; }
    }
#pragma unroll
  for (int i = 0; i < 4; i++)
    wfcv[i] = wfc[hs * 16 + (i >> 1) * 8 + h0 + (i & 1)];
  const float bfc = bfcp[0];

  // init fp32 states + fp16 copies into buffer 0
  float s0f[2][4], s1f[2][4];
#pragma unroll
  for (int bh = 0; bh < 2; bh++) {
    int gb = bt * 128 + blo + bh * 8;
#pragma unroll
    for (int i = 0; i < 4; i++) {
      int gh = hs * 16 + (i >> 1) * 8 + h0 + (i & 1);
      s0f[bh][i] = (gh < 385) ? z1[(size_t)gb * 385 + gh]
                              : y[(size_t)gb * 127 + (gh - 385)];
      s1f[bh][i] = hid1[(size_t)gb * 512 + gh];
    }
#pragma unroll
    for (int nt = 0; nt < 2; nt++) {
      int gh = hs * 16 + nt * 8 + h0;
      *(__half2*)&g_s0h[0][(size_t)gb * 512 + gh] =
          __floats2half2_rn(s0f[bh][nt * 2], s0f[bh][nt * 2 + 1]);
      *(__half2*)&g_s1h[0][(size_t)gb * 512 + gh] =
          __floats2half2_rn(s1f[bh][nt * 2], s1f[bh][nt * 2 + 1]);
    }
  }
  if (tid < 128) osm[tid] = x[bt * 128 + tid];
  cpwait<0>();
  __syncthreads();

  unsigned* barp = &g_bar[bt * 1024];
  groupbar(barp + 512);  // init states visible group-wide

  float Cg1[3][2][4], Cg2[3][2][4];

  for (int t = 0; t < 256; t++) {
    const int pb = t & 1, nb = pb ^ 1;
    const __half* s0p = g_s0h[pb] + (size_t)bt * 128 * 512;
    const __half* s1p = g_s1h[pb] + (size_t)bt * 128 * 512;

    // phase 1: gh1 = s0 @ whh1^T (slice 0), gh2 = s1 @ whh2^T (slice 2)
    gemm_slice(s0p, wsmu, stage_u32, tid, w, lane, Cg1);
    gemm_slice(s1p, wsmu + 24576, stage_u32, tid, w, lane, Cg2);

    // phase 2: cell-1 elementwise -> s0', write fp16 buf nb
    {
      float ob[2] = {osm[blo], osm[blo + 8]};
#pragma unroll
      for (int bh = 0; bh < 2; bh++) {
        int brow = blo + bh * 8;
#pragma unroll
        for (int i = 0; i < 4; i++) {
          int nt = i >> 1, e = bh * 2 + (i & 1);
          int yi = brow * 16 + nt * 8 + h0 + (i & 1);
          float gr = yctr[yi]        + ob[bh] * wc0[0][i] + Cg1[0][nt][e] + bhh1[0][i];
          float gz = yctr[2048 + yi] + ob[bh] * wc0[1][i] + Cg1[1][nt][e] + bhh1[1][i];
          float gn = yctr[4096 + yi] + ob[bh] * wc0[2][i];
          float r = sigm(gr), z = sigm(gz);
          float n = tanh_(gn + r * (Cg1[2][nt][e] + bhh1[2][i]));
          s0f[bh][i] = (1.f - z) * n + z * s0f[bh][i];
        }
        int gb = bt * 128 + brow;
#pragma unroll
        for (int nt = 0; nt < 2; nt++)
          *(__half2*)&g_s0h[nb][(size_t)gb * 512 + hs * 16 + nt * 8 + h0] =
              __floats2half2_rn(s0f[bh][nt * 2], s0f[bh][nt * 2 + 1]);
      }
    }
    groupbar(barp + t * 2);

    // phase 4: gi2 = s0' @ wih2^T (slice 1)  (reuse Cg1)
    gemm_slice(g_s0h[nb] + (size_t)bt * 128 * 512, wsmu + 12288, stage_u32,
               tid, w, lane, Cg1);

    // phase 5: cell-2 elementwise -> s1', fc partials
    {
#pragma unroll
      for (int bh = 0; bh < 2; bh++) {
        float p = 0.f;
#pragma unroll
        for (int i = 0; i < 4; i++) {
          int nt = i >> 1, e = bh * 2 + (i & 1);
          float r = sigm(Cg1[0][nt][e] + Cg2[0][nt][e] + brz2[0][i]);
          float z = sigm(Cg1[1][nt][e] + Cg2[1][nt][e] + brz2[1][i]);
          float n = tanh_(Cg1[2][nt][e] + bin2[i] + r * (Cg2[2][nt][e] + bhn2[i]));
          s1f[bh][i] = (1.f - z) * n + z * s1f[bh][i];
          p += s1f[bh][i] * wfcv[i];
        }
        int gb = bt * 128 + blo + bh * 8;
#pragma unroll
        for (int nt = 0; nt < 2; nt++)
          *(__half2*)&g_s1h[nb][(size_t)gb * 512 + hs * 16 + nt * 8 + h0] =
              __floats2half2_rn(s1f[bh][nt * 2], s1f[bh][nt * 2 + 1]);
        p += __shfl_xor_sync(0xffffffffu, p, 1);
        p += __shfl_xor_sync(0xffffffffu, p, 2);
        if ((lane & 3) == 0) __stcg(&g_fcpart[(size_t)gb * 32 + hs], p);
      }
    }
    groupbar(barp + t * 2 + 1);

    // phase 7: o = relu(bfc + sum partials)
    if (tid < 128) {
      const float* fp = &g_fcpart[(size_t)(bt * 128 + tid) * 32];
      float s = bfc;
#pragma unroll 8
      for (int k = 0; k < 32; k++) s += __ldcg(fp + k);
      float o = fmaxf(s, 0.f);
      osm[tid] = o;
      if (hs == 0) dout[(size_t)(bt * 128 + tid) * 256 + t] = o;
    }
  }
}

}  // namespace

extern "C" void kernel_launch(void* const* d_in, const int* in_sizes, int n_in,
                              void* d_out, int out_size) {
  const float* z1   = (const float*)d_in[0];
  const float* y    = (const float*)d_in[1];
  const float* x    = (const float*)d_in[2];
  const float* h1   = (const float*)d_in[3];
  const float* wih1 = (const float*)d_in[4];
  const float* whh1 = (const float*)d_in[5];
  const float* bih1 = (const float*)d_in[6];
  const float* bhh1 = (const float*)d_in[7];
  const float* wih2 = (const float*)d_in[8];
  const float* whh2 = (const float*)d_in[9];
  const float* bih2 = (const float*)d_in[10];
  const float* bhh2 = (const float*)d_in[11];
  const float* wfc  = (const float*)d_in[12];
  const float* bfc  = (const float*)d_in[13];

  cudaFuncSetAttribute(gen_main, cudaFuncAttributeMaxDynamicSharedMemorySize,
                       SMEM_BYTES);

  prep_zero<<<16, 256>>>();
  prep_pack<<<2304, 256>>>(whh1, wih2, whh2);
  prep_yctr<<<512, 256>>>(y, wih1, bih1);
  gen_main<<<128, 256, SMEM_BYTES>>>(z1, y, x, h1, wih1, bhh1, bih2, bhh2,
                                     wfc, bfc, (float*)d_out);
}